// round 15
// baseline (speedup 1.0000x reference)
#include <cuda_runtime.h>
#include <cuda_fp16.h>
#include <math.h>
#include <stdint.h>

#define BB    8
#define TT    512
#define CC    512
#define HH    8
#define DHD   64
#define LLAY  2
#define VV    512
#define MTOK  (BB*TT)
#define FF    (4*CC)
#define NSTEPS 4
#define QKVN  1536

// fp32 residual stream
__device__ float g_x[MTOK*CC];
// fp16 activations
__device__ __half g_xn[MTOK*CC];
__device__ __half g_qkv[MTOK*QKVN];
__device__ __half g_y[MTOK*CC];
__device__ __half g_h[MTOK*FF];
// fp16 weights [N,K]
#define WTOT 6553600
__device__ __half g_w[WTOT];
#define OQKV 0
#define OP   1572864
#define O1   2097152
#define O2   4194304
#define OHD  6291456
__device__ float g_bqkv[LLAY*QKVN];

// Q pre-scale: 0.125 * log2(e) folded into Wq/bq
#define SCQ 0.18033688011112042f

// ---------------------------------------------------------------------------
// helpers
// ---------------------------------------------------------------------------
__device__ __forceinline__ uint32_t smem_u32(const void* p) {
    uint32_t a;
    asm("{ .reg .u64 t; cvta.to.shared.u64 t, %1; cvt.u32.u64 %0, t; }"
        : "=r"(a) : "l"(p));
    return a;
}
__device__ __forceinline__ void ldm4(uint32_t* r, uint32_t addr) {
    asm volatile("ldmatrix.sync.aligned.m8n8.x4.shared.b16 {%0,%1,%2,%3}, [%4];"
                 : "=r"(r[0]), "=r"(r[1]), "=r"(r[2]), "=r"(r[3]) : "r"(addr));
}
__device__ __forceinline__ void ldm4t(uint32_t* r, uint32_t addr) {
    asm volatile("ldmatrix.sync.aligned.m8n8.x4.trans.shared.b16 {%0,%1,%2,%3}, [%4];"
                 : "=r"(r[0]), "=r"(r[1]), "=r"(r[2]), "=r"(r[3]) : "r"(addr));
}
__device__ __forceinline__ void mma16816(float* c, const uint32_t* a,
                                         uint32_t b0, uint32_t b1) {
    asm volatile("mma.sync.aligned.m16n8k16.row.col.f32.f16.f16.f32 "
                 "{%0,%1,%2,%3}, {%4,%5,%6,%7}, {%8,%9}, {%0,%1,%2,%3};"
                 : "+f"(c[0]), "+f"(c[1]), "+f"(c[2]), "+f"(c[3])
                 : "r"(a[0]), "r"(a[1]), "r"(a[2]), "r"(a[3]),
                   "r"(b0), "r"(b1));
}
__device__ __forceinline__ void cpa16(uint32_t s, const void* g) {
    asm volatile("cp.async.cg.shared.global [%0], [%1], 16;" :: "r"(s), "l"(g));
}
__device__ __forceinline__ void cp_commit() {
    asm volatile("cp.async.commit_group;" ::: "memory");
}
template<int W> __device__ __forceinline__ void cp_wait() {
    asm volatile("cp.async.wait_group %0;" :: "n"(W) : "memory");
}
__device__ __forceinline__ uint32_t pk2h(float a, float b) {
    __half2 h = __floats2half2_rn(a, b);
    return *(uint32_t*)&h;
}

// ---------------------------------------------------------------------------
// Unified preprocessing: 13 weight transposes (with optional scale) + bias
// pack (bq scaled) + embed, one launch
// ---------------------------------------------------------------------------
struct PrepArgs {
    const float* src[14];
    size_t dst[14];
    int K[14], N[14];
    float scl[14];
    int off[16];
    const float* bq; const float* bk; const float* bv;
};

__global__ void prep_kernel(PrepArgs a, __half* __restrict__ Wt,
                            float* __restrict__ bdst,
                            const int* __restrict__ idx,
                            const float* __restrict__ tok,
                            const float* __restrict__ pos,
                            float* __restrict__ x)
{
    __shared__ float t[32][33];
    int bid = blockIdx.x;
    int z = 0;
    while (bid >= a.off[z + 1]) ++z;
    int local = bid - a.off[z];
    int tx = threadIdx.x, ty = threadIdx.y;
    int tid = ty * 32 + tx;

    if (z == 14) {
        #pragma unroll
        for (int k = 0; k < 2; ++k) {
            int g4 = local * 512 + tid + k * 256;
            int row = g4 >> 7, c4 = g4 & 127;
            int tk = idx[row];
            float4 tv = ((const float4*)tok)[tk * 128 + c4];
            float4 pv = ((const float4*)pos)[(row & (TT - 1)) * 128 + c4];
            float4 o;
            o.x = tv.x + pv.x; o.y = tv.y + pv.y;
            o.z = tv.z + pv.z; o.w = tv.w + pv.w;
            ((float4*)x)[g4] = o;
        }
        return;
    }
    if (z == 13) {
        int i = local * 256 + tid;
        int l = i / QKVN, j = i % QKVN;
        float v = (j < 512) ? a.bq[l*CC + j] * SCQ
                : (j < 1024) ? a.bk[l*CC + (j - 512)]
                : a.bv[l*CC + (j - 1024)];
        bdst[l*QKVN + j] = v;
        return;
    }

    int K = a.K[z], N = a.N[z];
    float sc = a.scl[z];
    int ntx = N / 32;
    int n0 = (local % ntx) * 32, k0 = (local / ntx) * 32;
    const float* W = a.src[z];
    __half* dstp = Wt + a.dst[z];
    #pragma unroll
    for (int j = 0; j < 32; j += 8)
        t[ty + j][tx] = W[(size_t)(k0 + ty + j) * N + n0 + tx];
    __syncthreads();
    #pragma unroll
    for (int j = 0; j < 32; j += 8)
        dstp[(size_t)(n0 + ty + j) * K + k0 + tx] =
            __float2half_rn(t[tx][ty + j] * sc);
}

// ---------------------------------------------------------------------------
// GEMM template (measured-best): tile 128xBN, BK=64, BN*2 threads, 3-stage
// cp.async pipeline, fragment double-buffering.
// ---------------------------------------------------------------------------
#define GSTRIDE 72
#define GROWB   (GSTRIDE*2)
#define GATILEB (128*GROWB)                 // 18432

template<int BN>
__global__ __launch_bounds__(BN*2, 2)
void gemm_t(const __half* __restrict__ Ah,
            const __half* __restrict__ Bh,
            const float* __restrict__ bias, const float* __restrict__ res,
            float* __restrict__ outf, __half* __restrict__ outh,
            int N, int K, int do_gelu)
{
    constexpr int NTHR   = BN * 2;
    constexpr int BTILEB = BN * GROWB;
    constexpr int STG    = GATILEB + BTILEB;
    constexpr int ACH    = 1024 / NTHR;
    constexpr int BCH    = (BN * 8) / NTHR;

    extern __shared__ char smem[];
    const uint32_t sb = smem_u32(smem);
    const int tid = threadIdx.x, lane = tid & 31, wid = tid >> 5;
    const int m0 = (BN == 128) ? (wid >> 1) * 32 : wid * 32;
    const int n0 = (BN == 128) ? (wid & 1) * 64 : 0;
    const int bn = blockIdx.x * BN, bm = blockIdx.y * 128;

    const int lr = lane & 7;
    const uint32_t aoff0 = (uint32_t)((m0 + ((lane>>3)&1)*8 + lr) * GSTRIDE + (lane>>4)*8) * 2;
    const uint32_t aoff1 = aoff0 + 16 * GROWB;
    const uint32_t boff0 = (uint32_t)((n0 + (lane>>4)*8 + lr) * GSTRIDE + ((lane>>3)&1)*8) * 2
                         + GATILEB;

    float acc[2][8][4];
    #pragma unroll
    for (int mt = 0; mt < 2; ++mt)
        #pragma unroll
        for (int nt = 0; nt < 8; ++nt)
            #pragma unroll
            for (int j = 0; j < 4; ++j) acc[mt][nt][j] = 0.0f;

    auto loadStage = [&](int s, int kt) {
        uint32_t base = sb + s * STG;
        int k0 = kt * 64;
        #pragma unroll
        for (int i = 0; i < ACH; ++i) {
            int id = tid + i * NTHR, row = id >> 3, c = id & 7;
            cpa16(base + (uint32_t)row * GROWB + c * 16,
                  Ah + (size_t)(bm + row) * K + k0 + c * 8);
        }
        #pragma unroll
        for (int i = 0; i < BCH; ++i) {
            int id = tid + i * NTHR, row = id >> 3, c = id & 7;
            cpa16(base + GATILEB + (uint32_t)row * GROWB + c * 16,
                  Bh + (size_t)(bn + row) * K + k0 + c * 8);
        }
        cp_commit();
    };

    auto compute = [&](int s) {
        uint32_t base = sb + s * STG;
        uint32_t a0[2][4], a1[2][4], bfr[2][4][4];
        ldm4(a0[0], base + aoff0);
        ldm4(a1[0], base + aoff1);
        #pragma unroll
        for (int p = 0; p < 4; ++p)
            ldm4(bfr[0][p], base + boff0 + p * (16 * GROWB));
        #pragma unroll
        for (int ks = 0; ks < 4; ++ks) {
            const int cur = ks & 1, nxt = cur ^ 1;
            if (ks < 3) {
                uint32_t kb = (ks + 1) * 32;
                ldm4(a0[nxt], base + aoff0 + kb);
                ldm4(a1[nxt], base + aoff1 + kb);
                #pragma unroll
                for (int p = 0; p < 4; ++p)
                    ldm4(bfr[nxt][p], base + boff0 + p * (16 * GROWB) + kb);
            }
            #pragma unroll
            for (int p = 0; p < 4; ++p) {
                mma16816(acc[0][p*2],   a0[cur], bfr[cur][p][0], bfr[cur][p][1]);
                mma16816(acc[0][p*2+1], a0[cur], bfr[cur][p][2], bfr[cur][p][3]);
                mma16816(acc[1][p*2],   a1[cur], bfr[cur][p][0], bfr[cur][p][1]);
                mma16816(acc[1][p*2+1], a1[cur], bfr[cur][p][2], bfr[cur][p][3]);
            }
        }
    };

    const int NT = K / 64;
    loadStage(0, 0);
    loadStage(1, 1);
    int s_c = 0, s_l = 2;
    for (int kt = 0; kt < NT; ++kt) {
        cp_wait<1>();
        __syncthreads();
        if (kt + 2 < NT) {
            loadStage(s_l, kt + 2);
            if (++s_l == 3) s_l = 0;
        }
        compute(s_c);
        if (++s_c == 3) s_c = 0;
    }

    #pragma unroll
    for (int mt = 0; mt < 2; ++mt) {
        int r0 = bm + m0 + mt * 16 + (lane >> 2);
        #pragma unroll
        for (int nt = 0; nt < 8; ++nt) {
            int col = bn + n0 + nt * 8 + (lane & 3) * 2;
            float v0 = acc[mt][nt][0], v1 = acc[mt][nt][1];
            float v2 = acc[mt][nt][2], v3 = acc[mt][nt][3];
            if (bias) {
                float2 bv = *(const float2*)(bias + col);
                v0 += bv.x; v1 += bv.y; v2 += bv.x; v3 += bv.y;
            }
            if (do_gelu) {
                v0 = 0.5f * v0 * (1.0f + erff(v0 * 0.70710678f));
                v1 = 0.5f * v1 * (1.0f + erff(v1 * 0.70710678f));
                v2 = 0.5f * v2 * (1.0f + erff(v2 * 0.70710678f));
                v3 = 0.5f * v3 * (1.0f + erff(v3 * 0.70710678f));
            }
            size_t g0 = (size_t)r0 * N + col;
            size_t g1 = (size_t)(r0 + 8) * N + col;
            if (outf) {
                if (res) {
                    float2 ra = *(const float2*)(res + g0);
                    float2 rb = *(const float2*)(res + g1);
                    v0 += ra.x; v1 += ra.y; v2 += rb.x; v3 += rb.y;
                }
                float2 o0; o0.x = v0; o0.y = v1;
                float2 o1; o1.x = v2; o1.y = v3;
                *(float2*)(outf + g0) = o0;
                *(float2*)(outf + g1) = o1;
            } else {
                *(uint32_t*)(outh + g0) = pk2h(v0, v1);
                *(uint32_t*)(outh + g1) = pk2h(v2, v3);
            }
        }
    }
}

#define GSMEM128 (3*(GATILEB + 128*GROWB))   // 110592
#define GSMEM64  (3*(GATILEB + 64*GROWB))    // 82944

// ---------------------------------------------------------------------------
// Flash attention, fp16 mma.sync, no online max, Q pre-scaled at prep.
// 128 q per CTA, 256 threads (8 warps x 16 q-rows). K/V double-buffered.
// ---------------------------------------------------------------------------
#define ASTR   72
#define AQTILE (128*ASTR*2)         // 18432 (Q: 128 rows)
#define AKTILE (64*ASTR*2)          // 9216  (K or V: 64 rows)
#define ASTG   (2*AKTILE)           // 18432 per stage
#define ASMEM  (AQTILE + 2*ASTG)    // 55296

__global__ __launch_bounds__(256)
void attn_hp(const __half* __restrict__ QKV,
             __half* __restrict__ Y)
{
    extern __shared__ char smem[];
    const uint32_t sb = smem_u32(smem);
    const int tid = threadIdx.x, lane = tid & 31, wid = tid >> 5;
    const int q0 = blockIdx.x * 128, h = blockIdx.y, b = blockIdx.z;
    const size_t rowbase = (size_t)b * TT;
    const uint32_t kvbase = sb + AQTILE;

    #pragma unroll
    for (int i = 0; i < 4; ++i) {
        int id = tid + i * 256, row = id >> 3, c = id & 7;
        cpa16(sb + (uint32_t)row * 144 + c * 16,
              QKV + (rowbase + q0 + row) * QKVN + h * DHD + c * 8);
    }
    auto loadKV = [&](int s, int kt) {
        uint32_t base = kvbase + s * ASTG;
        #pragma unroll
        for (int i = 0; i < 2; ++i) {
            int id = tid + i * 256, row = id >> 3, c = id & 7;
            size_t gk = (rowbase + kt * 64 + row) * QKVN + 512 + h * DHD + c * 8;
            cpa16(base + (uint32_t)row * 144 + c * 16,          QKV + gk);
            cpa16(base + AKTILE + (uint32_t)row * 144 + c * 16, QKV + gk + 512);
        }
        cp_commit();
    };
    loadKV(0, 0);

    const int lr = lane & 7;
    const uint32_t aoffQ = (uint32_t)((wid*16 + ((lane>>3)&1)*8 + lr) * ASTR + (lane>>4)*8) * 2;
    uint32_t boffK[4];
    #pragma unroll
    for (int p = 0; p < 4; ++p)
        boffK[p] = (uint32_t)((p*16 + (lane>>4)*8 + lr) * ASTR + ((lane>>3)&1)*8) * 2;
    const uint32_t voffV = (uint32_t)((lr + 8*((lane>>3)&1)) * ASTR + 8*(lane>>4)) * 2;

    uint32_t qf[4][4];
    float accs[8][4], acco[8][4];
    #pragma unroll
    for (int nt = 0; nt < 8; ++nt)
        #pragma unroll
        for (int j = 0; j < 4; ++j) acco[nt][j] = 0.0f;
    float lA = 0.0f, lB = 0.0f;

    const int NTK = TT / 64;
    for (int kt = 0; kt < NTK; ++kt) {
        cp_wait<0>();
        __syncthreads();
        if (kt + 1 < NTK) loadKV((kt + 1) & 1, kt + 1);
        if (kt == 0) {
            #pragma unroll
            for (int ks = 0; ks < 4; ++ks) ldm4(qf[ks], sb + aoffQ + ks * 32);
        }
        uint32_t base = kvbase + (kt & 1) * ASTG;

        // ---- S = Q @ K^T (Q pre-scaled by 0.125*log2e) ----
        #pragma unroll
        for (int nt = 0; nt < 8; ++nt)
            #pragma unroll
            for (int j = 0; j < 4; ++j) accs[nt][j] = 0.0f;
        #pragma unroll
        for (int ks = 0; ks < 4; ++ks) {
            uint32_t kb = ks * 32;
            uint32_t kf[4][4];
            #pragma unroll
            for (int p = 0; p < 4; ++p) ldm4(kf[p], base + boffK[p] + kb);
            #pragma unroll
            for (int p = 0; p < 4; ++p) {
                mma16816(accs[p*2],   qf[ks], kf[p][0], kf[p][1]);
                mma16816(accs[p*2+1], qf[ks], kf[p][2], kf[p][3]);
            }
        }

        // ---- P = exp2(S) directly ----
        #pragma unroll
        for (int nt = 0; nt < 8; ++nt) {
            float p0 = exp2f(accs[nt][0]);
            float p1 = exp2f(accs[nt][1]);
            float p2 = exp2f(accs[nt][2]);
            float p3 = exp2f(accs[nt][3]);
            accs[nt][0] = p0; accs[nt][1] = p1;
            accs[nt][2] = p2; accs[nt][3] = p3;
            lA += p0 + p1; lB += p2 + p3;
        }

        // ---- O += P @ V ----
        #pragma unroll
        for (int j = 0; j < 4; ++j) {
            uint32_t pa[4];
            pa[0] = pk2h(accs[2*j][0],   accs[2*j][1]);
            pa[1] = pk2h(accs[2*j][2],   accs[2*j][3]);
            pa[2] = pk2h(accs[2*j+1][0], accs[2*j+1][1]);
            pa[3] = pk2h(accs[2*j+1][2], accs[2*j+1][3]);
            uint32_t vrow = j * 16 * (ASTR * 2);
            #pragma unroll
            for (int qd = 0; qd < 4; ++qd) {
                uint32_t vf[4];
                ldm4t(vf, base + AKTILE + voffV + vrow + qd * 32);
                mma16816(acco[qd*2],   pa, vf[0], vf[1]);
                mma16816(acco[qd*2+1], pa, vf[2], vf[3]);
            }
        }
    }

    lA += __shfl_xor_sync(0xffffffffu, lA, 1);
    lA += __shfl_xor_sync(0xffffffffu, lA, 2);
    lB += __shfl_xor_sync(0xffffffffu, lB, 1);
    lB += __shfl_xor_sync(0xffffffffu, lB, 2);

    float invA = 1.0f / lA, invB = 1.0f / lB;
    int rA = q0 + wid * 16 + (lane >> 2);
    #pragma unroll
    for (int nt = 0; nt < 8; ++nt) {
        int col = h * DHD + nt * 8 + (lane & 3) * 2;
        size_t g0 = (rowbase + rA) * CC + col;
        size_t g1 = (rowbase + rA + 8) * CC + col;
        *(uint32_t*)(Y + g0) = pk2h(acco[nt][0] * invA, acco[nt][1] * invA);
        *(uint32_t*)(Y + g1) = pk2h(acco[nt][2] * invB, acco[nt][3] * invB);
    }
}

// ---------------------------------------------------------------------------
// LayerNorm: warp-per-row, 8 rows/CTA
// ---------------------------------------------------------------------------
__global__ __launch_bounds__(256)
void ln_kernel(const float* __restrict__ x,
               const float* __restrict__ g,
               const float* __restrict__ b,
               __half* __restrict__ oh)
{
    const int lane = threadIdx.x & 31, wid = threadIdx.x >> 5;
    const int row = blockIdx.x * 8 + wid;
    const float4* xr = (const float4*)(x + (size_t)row * CC);

    float4 v[4];
    float s = 0.0f, s2 = 0.0f;
    #pragma unroll
    for (int i = 0; i < 4; ++i) {
        v[i] = xr[lane + i * 32];
        s  += v[i].x + v[i].y + v[i].z + v[i].w;
        s2 += v[i].x*v[i].x + v[i].y*v[i].y + v[i].z*v[i].z + v[i].w*v[i].w;
    }
    #pragma unroll
    for (int o = 16; o; o >>= 1) {
        s  += __shfl_xor_sync(0xffffffffu, s,  o);
        s2 += __shfl_xor_sync(0xffffffffu, s2, o);
    }
    float mu = s * (1.0f / CC);
    float var = s2 * (1.0f / CC) - mu * mu;
    float rstd = rsqrtf(var + 1e-5f);

    uint2* orow = (uint2*)(oh + (size_t)row * CC);
    #pragma unroll
    for (int i = 0; i < 4; ++i) {
        float4 gg = ((const float4*)g)[lane + i * 32];
        float4 bb = ((const float4*)b)[lane + i * 32];
        float h0 = (v[i].x - mu) * rstd * gg.x + bb.x;
        float h1 = (v[i].y - mu) * rstd * gg.y + bb.y;
        float h2 = (v[i].z - mu) * rstd * gg.z + bb.z;
        float h3 = (v[i].w - mu) * rstd * gg.w + bb.w;
        uint2 o; o.x = pk2h(h0, h1); o.y = pk2h(h2, h3);
        orow[lane + i * 32] = o;
    }
}

// ---------------------------------------------------------------------------
// Launch
// ---------------------------------------------------------------------------
extern "C" void kernel_launch(void* const* d_in, const int* in_sizes, int n_in,
                              void* d_out, int out_size)
{
    const int*   idx  = (const int*)  d_in[0];
    const float* tok  = (const float*)d_in[1];
    const float* pos  = (const float*)d_in[2];
    const float* ln1g = (const float*)d_in[3];
    const float* ln1b = (const float*)d_in[4];
    const float* Wq   = (const float*)d_in[5];
    const float* bq   = (const float*)d_in[6];
    const float* Wk   = (const float*)d_in[7];
    const float* bk   = (const float*)d_in[8];
    const float* Wv   = (const float*)d_in[9];
    const float* bv   = (const float*)d_in[10];
    const float* Wp   = (const float*)d_in[11];
    const float* bp   = (const float*)d_in[12];
    const float* ln2g = (const float*)d_in[13];
    const float* ln2b = (const float*)d_in[14];
    const float* W1   = (const float*)d_in[15];
    const float* b1   = (const float*)d_in[16];
    const float* W2   = (const float*)d_in[17];
    const float* b2   = (const float*)d_in[18];
    const float* lnfg = (const float*)d_in[19];
    const float* lnfb = (const float*)d_in[20];
    const float* Whd  = (const float*)d_in[21];
    float* out = (float*)d_out;

    float *x, *bqkv;
    __half *xn, *qkv, *y, *h, *w;
    cudaGetSymbolAddress((void**)&x,    g_x);
    cudaGetSymbolAddress((void**)&xn,   g_xn);
    cudaGetSymbolAddress((void**)&qkv,  g_qkv);
    cudaGetSymbolAddress((void**)&y,    g_y);
    cudaGetSymbolAddress((void**)&h,    g_h);
    cudaGetSymbolAddress((void**)&w,    g_w);
    cudaGetSymbolAddress((void**)&bqkv, g_bqkv);

    cudaFuncSetAttribute(gemm_t<128>, cudaFuncAttributeMaxDynamicSharedMemorySize, GSMEM128);
    cudaFuncSetAttribute(gemm_t<64>,  cudaFuncAttributeMaxDynamicSharedMemorySize, GSMEM64);
    cudaFuncSetAttribute(attn_hp, cudaFuncAttributeMaxDynamicSharedMemorySize, ASMEM);

    // ---- prep args: 13 weights (+scale) + bias + embed ----
    PrepArgs pa;
    int zi = 0;
    for (int l = 0; l < LLAY; l++) {
        pa.src[zi] = Wq + (size_t)l*CC*CC; pa.dst[zi] = OQKV + (size_t)l*QKVN*CC;           pa.K[zi]=CC; pa.N[zi]=CC; pa.scl[zi]=SCQ;  zi++;
        pa.src[zi] = Wk + (size_t)l*CC*CC; pa.dst[zi] = OQKV + (size_t)l*QKVN*CC + 512*CC;  pa.K[zi]=CC; pa.N[zi]=CC; pa.scl[zi]=1.0f; zi++;
        pa.src[zi] = Wv + (size_t)l*CC*CC; pa.dst[zi] = OQKV + (size_t)l*QKVN*CC + 1024*CC; pa.K[zi]=CC; pa.N[zi]=CC; pa.scl[zi]=1.0f; zi++;
        pa.src[zi] = Wp + (size_t)l*CC*CC; pa.dst[zi] = OP + (size_t)l*CC*CC;               pa.K[zi]=CC; pa.N[zi]=CC; pa.scl[zi]=1.0f; zi++;
        pa.src[zi] = W1 + (size_t)l*CC*FF; pa.dst[zi] = O1 + (size_t)l*CC*FF;               pa.K[zi]=CC; pa.N[zi]=FF; pa.scl[zi]=1.0f; zi++;
        pa.src[zi] = W2 + (size_t)l*FF*CC; pa.dst[zi] = O2 + (size_t)l*FF*CC;               pa.K[zi]=FF; pa.N[zi]=CC; pa.scl[zi]=1.0f; zi++;
    }
    pa.src[zi] = Whd; pa.dst[zi] = OHD; pa.K[zi]=CC; pa.N[zi]=VV; pa.scl[zi]=1.0f; zi++;
    pa.K[13] = 0; pa.N[13] = 0; pa.src[13] = nullptr; pa.dst[13] = 0; pa.scl[13] = 1.0f;
    pa.bq = bq; pa.bk = bk; pa.bv = bv;
    pa.off[0] = 0;
    for (int z = 0; z < 13; z++)
        pa.off[z + 1] = pa.off[z] + (pa.N[z] / 32) * (pa.K[z] / 32);
    pa.off[14] = pa.off[13] + 12;
    pa.off[15] = pa.off[14] + 1024;
    int nblocks = pa.off[15];

    dim3 tb(32, 8);
    dim3 gQKV64(QKVN/64, MTOK/128);  // (24, 32) = 768 CTAs, BN=64
    dim3 gF(FF/128, MTOK/128);       // (16, 32) BN=128
    dim3 gC64(CC/64, MTOK/128);      // (8, 32)  BN=64
    dim3 gA(TT/128, HH, BB);         // (4, 8, 8) = 256
    dim3 gLN(MTOK/8);

    // launch 0: prep(+embed), 1: ln, 2: qkv, 3: attn (ncu capture target)
    prep_kernel<<<nblocks, tb>>>(pa, w, bqkv, idx, tok, pos, x);

    for (int s = 0; s < NSTEPS; s++) {
        for (int l = 0; l < LLAY; l++) {
            size_t lq = OQKV + (size_t)l * QKVN * CC;
            size_t lp = OP + (size_t)l * CC * CC;
            size_t l1 = O1 + (size_t)l * CC * FF;
            size_t l2 = O2 + (size_t)l * FF * CC;
            ln_kernel<<<gLN, 256>>>(x, ln1g + l*CC, ln1b + l*CC, xn);
            gemm_t<64><<<gQKV64, 128, GSMEM64>>>(xn, w + lq, bqkv + l*QKVN, nullptr,
                                                 nullptr, qkv, QKVN, CC, 0);
            attn_hp<<<gA, 256, ASMEM>>>(qkv, y);
            gemm_t<64><<<gC64, 128, GSMEM64>>>(y, w + lp, bp + l*CC, x,
                                               x, nullptr, CC, CC, 0);
            ln_kernel<<<gLN, 256>>>(x, ln2g + l*CC, ln2b + l*CC, xn);
            gemm_t<128><<<gF, 256, GSMEM128>>>(xn, w + l1, b1 + l*FF, nullptr,
                                               nullptr, h, FF, CC, 1);
            gemm_t<64><<<gC64, 128, GSMEM64>>>(h, w + l2, b2 + l*CC, x,
                                               x, nullptr, CC, FF, 0);
        }
    }

    ln_kernel<<<gLN, 256>>>(x, lnfg, lnfb, xn);
    gemm_t<64><<<gC64, 128, GSMEM64>>>(xn, w + OHD, nullptr, nullptr,
                                       out, nullptr, VV, CC, 0);
}

// round 16
// speedup vs baseline: 1.0197x; 1.0197x over previous
#include <cuda_runtime.h>
#include <cuda_fp16.h>
#include <math.h>
#include <stdint.h>

#define BB    8
#define TT    512
#define CC    512
#define HH    8
#define DHD   64
#define LLAY  2
#define VV    512
#define MTOK  (BB*TT)
#define FF    (4*CC)
#define NSTEPS 4
#define QKVN  1536

// fp32 residual stream
__device__ float g_x[MTOK*CC];
// fp16 activations
__device__ __half g_xn[MTOK*CC];
__device__ __half g_qkv[MTOK*QKVN];
__device__ __half g_y[MTOK*CC];
__device__ __half g_h[MTOK*FF];
// fp16 weights [N,K]
#define WTOT 6553600
__device__ __half g_w[WTOT];
#define OQKV 0
#define OP   1572864
#define O1   2097152
#define O2   4194304
#define OHD  6291456
__device__ float g_bqkv[LLAY*QKVN];

// Q pre-scale: 0.125 * log2(e) folded into Wq/bq
#define SCQ 0.18033688011112042f

// ---------------------------------------------------------------------------
// helpers
// ---------------------------------------------------------------------------
__device__ __forceinline__ uint32_t smem_u32(const void* p) {
    uint32_t a;
    asm("{ .reg .u64 t; cvta.to.shared.u64 t, %1; cvt.u32.u64 %0, t; }"
        : "=r"(a) : "l"(p));
    return a;
}
__device__ __forceinline__ void ldm4(uint32_t* r, uint32_t addr) {
    asm volatile("ldmatrix.sync.aligned.m8n8.x4.shared.b16 {%0,%1,%2,%3}, [%4];"
                 : "=r"(r[0]), "=r"(r[1]), "=r"(r[2]), "=r"(r[3]) : "r"(addr));
}
__device__ __forceinline__ void ldm4t(uint32_t* r, uint32_t addr) {
    asm volatile("ldmatrix.sync.aligned.m8n8.x4.trans.shared.b16 {%0,%1,%2,%3}, [%4];"
                 : "=r"(r[0]), "=r"(r[1]), "=r"(r[2]), "=r"(r[3]) : "r"(addr));
}
__device__ __forceinline__ void mma16816(float* c, const uint32_t* a,
                                         uint32_t b0, uint32_t b1) {
    asm volatile("mma.sync.aligned.m16n8k16.row.col.f32.f16.f16.f32 "
                 "{%0,%1,%2,%3}, {%4,%5,%6,%7}, {%8,%9}, {%0,%1,%2,%3};"
                 : "+f"(c[0]), "+f"(c[1]), "+f"(c[2]), "+f"(c[3])
                 : "r"(a[0]), "r"(a[1]), "r"(a[2]), "r"(a[3]),
                   "r"(b0), "r"(b1));
}
__device__ __forceinline__ void cpa16(uint32_t s, const void* g) {
    asm volatile("cp.async.cg.shared.global [%0], [%1], 16;" :: "r"(s), "l"(g));
}
__device__ __forceinline__ void cp_commit() {
    asm volatile("cp.async.commit_group;" ::: "memory");
}
template<int W> __device__ __forceinline__ void cp_wait() {
    asm volatile("cp.async.wait_group %0;" :: "n"(W) : "memory");
}
__device__ __forceinline__ uint32_t pk2h(float a, float b) {
    __half2 h = __floats2half2_rn(a, b);
    return *(uint32_t*)&h;
}

// ---------------------------------------------------------------------------
// Unified preprocessing: 13 weight transposes (with optional scale) + bias
// pack (bq scaled) + embed, one launch
// ---------------------------------------------------------------------------
struct PrepArgs {
    const float* src[14];
    size_t dst[14];
    int K[14], N[14];
    float scl[14];
    int off[16];
    const float* bq; const float* bk; const float* bv;
};

__global__ void prep_kernel(PrepArgs a, __half* __restrict__ Wt,
                            float* __restrict__ bdst,
                            const int* __restrict__ idx,
                            const float* __restrict__ tok,
                            const float* __restrict__ pos,
                            float* __restrict__ x)
{
    __shared__ float t[32][33];
    int bid = blockIdx.x;
    int z = 0;
    while (bid >= a.off[z + 1]) ++z;
    int local = bid - a.off[z];
    int tx = threadIdx.x, ty = threadIdx.y;
    int tid = ty * 32 + tx;

    if (z == 14) {
        #pragma unroll
        for (int k = 0; k < 2; ++k) {
            int g4 = local * 512 + tid + k * 256;
            int row = g4 >> 7, c4 = g4 & 127;
            int tk = idx[row];
            float4 tv = ((const float4*)tok)[tk * 128 + c4];
            float4 pv = ((const float4*)pos)[(row & (TT - 1)) * 128 + c4];
            float4 o;
            o.x = tv.x + pv.x; o.y = tv.y + pv.y;
            o.z = tv.z + pv.z; o.w = tv.w + pv.w;
            ((float4*)x)[g4] = o;
        }
        return;
    }
    if (z == 13) {
        int i = local * 256 + tid;
        int l = i / QKVN, j = i % QKVN;
        float v = (j < 512) ? a.bq[l*CC + j] * SCQ
                : (j < 1024) ? a.bk[l*CC + (j - 512)]
                : a.bv[l*CC + (j - 1024)];
        bdst[l*QKVN + j] = v;
        return;
    }

    int K = a.K[z], N = a.N[z];
    float sc = a.scl[z];
    int ntx = N / 32;
    int n0 = (local % ntx) * 32, k0 = (local / ntx) * 32;
    const float* W = a.src[z];
    __half* dstp = Wt + a.dst[z];
    #pragma unroll
    for (int j = 0; j < 32; j += 8)
        t[ty + j][tx] = W[(size_t)(k0 + ty + j) * N + n0 + tx];
    __syncthreads();
    #pragma unroll
    for (int j = 0; j < 32; j += 8)
        dstp[(size_t)(n0 + ty + j) * K + k0 + tx] =
            __float2half_rn(t[tx][ty + j] * sc);
}

// ---------------------------------------------------------------------------
// GEMM template (measured-best): tile 128xBN, BK=64, BN*2 threads, 3-stage
// cp.async pipeline, fragment double-buffering.
// ---------------------------------------------------------------------------
#define GSTRIDE 72
#define GROWB   (GSTRIDE*2)
#define GATILEB (128*GROWB)                 // 18432

template<int BN>
__global__ __launch_bounds__(BN*2, 2)
void gemm_t(const __half* __restrict__ Ah,
            const __half* __restrict__ Bh,
            const float* __restrict__ bias, const float* __restrict__ res,
            float* __restrict__ outf, __half* __restrict__ outh,
            int N, int K, int do_gelu)
{
    constexpr int NTHR   = BN * 2;
    constexpr int BTILEB = BN * GROWB;
    constexpr int STG    = GATILEB + BTILEB;
    constexpr int ACH    = 1024 / NTHR;
    constexpr int BCH    = (BN * 8) / NTHR;

    extern __shared__ char smem[];
    const uint32_t sb = smem_u32(smem);
    const int tid = threadIdx.x, lane = tid & 31, wid = tid >> 5;
    const int m0 = (BN == 128) ? (wid >> 1) * 32 : wid * 32;
    const int n0 = (BN == 128) ? (wid & 1) * 64 : 0;
    const int bn = blockIdx.x * BN, bm = blockIdx.y * 128;

    const int lr = lane & 7;
    const uint32_t aoff0 = (uint32_t)((m0 + ((lane>>3)&1)*8 + lr) * GSTRIDE + (lane>>4)*8) * 2;
    const uint32_t aoff1 = aoff0 + 16 * GROWB;
    const uint32_t boff0 = (uint32_t)((n0 + (lane>>4)*8 + lr) * GSTRIDE + ((lane>>3)&1)*8) * 2
                         + GATILEB;

    float acc[2][8][4];
    #pragma unroll
    for (int mt = 0; mt < 2; ++mt)
        #pragma unroll
        for (int nt = 0; nt < 8; ++nt)
            #pragma unroll
            for (int j = 0; j < 4; ++j) acc[mt][nt][j] = 0.0f;

    auto loadStage = [&](int s, int kt) {
        uint32_t base = sb + s * STG;
        int k0 = kt * 64;
        #pragma unroll
        for (int i = 0; i < ACH; ++i) {
            int id = tid + i * NTHR, row = id >> 3, c = id & 7;
            cpa16(base + (uint32_t)row * GROWB + c * 16,
                  Ah + (size_t)(bm + row) * K + k0 + c * 8);
        }
        #pragma unroll
        for (int i = 0; i < BCH; ++i) {
            int id = tid + i * NTHR, row = id >> 3, c = id & 7;
            cpa16(base + GATILEB + (uint32_t)row * GROWB + c * 16,
                  Bh + (size_t)(bn + row) * K + k0 + c * 8);
        }
        cp_commit();
    };

    auto compute = [&](int s) {
        uint32_t base = sb + s * STG;
        uint32_t a0[2][4], a1[2][4], bfr[2][4][4];
        ldm4(a0[0], base + aoff0);
        ldm4(a1[0], base + aoff1);
        #pragma unroll
        for (int p = 0; p < 4; ++p)
            ldm4(bfr[0][p], base + boff0 + p * (16 * GROWB));
        #pragma unroll
        for (int ks = 0; ks < 4; ++ks) {
            const int cur = ks & 1, nxt = cur ^ 1;
            if (ks < 3) {
                uint32_t kb = (ks + 1) * 32;
                ldm4(a0[nxt], base + aoff0 + kb);
                ldm4(a1[nxt], base + aoff1 + kb);
                #pragma unroll
                for (int p = 0; p < 4; ++p)
                    ldm4(bfr[nxt][p], base + boff0 + p * (16 * GROWB) + kb);
            }
            #pragma unroll
            for (int p = 0; p < 4; ++p) {
                mma16816(acc[0][p*2],   a0[cur], bfr[cur][p][0], bfr[cur][p][1]);
                mma16816(acc[0][p*2+1], a0[cur], bfr[cur][p][2], bfr[cur][p][3]);
                mma16816(acc[1][p*2],   a1[cur], bfr[cur][p][0], bfr[cur][p][1]);
                mma16816(acc[1][p*2+1], a1[cur], bfr[cur][p][2], bfr[cur][p][3]);
            }
        }
    };

    const int NT = K / 64;
    loadStage(0, 0);
    loadStage(1, 1);
    int s_c = 0, s_l = 2;
    for (int kt = 0; kt < NT; ++kt) {
        cp_wait<1>();
        __syncthreads();
        if (kt + 2 < NT) {
            loadStage(s_l, kt + 2);
            if (++s_l == 3) s_l = 0;
        }
        compute(s_c);
        if (++s_c == 3) s_c = 0;
    }

    #pragma unroll
    for (int mt = 0; mt < 2; ++mt) {
        int r0 = bm + m0 + mt * 16 + (lane >> 2);
        #pragma unroll
        for (int nt = 0; nt < 8; ++nt) {
            int col = bn + n0 + nt * 8 + (lane & 3) * 2;
            float v0 = acc[mt][nt][0], v1 = acc[mt][nt][1];
            float v2 = acc[mt][nt][2], v3 = acc[mt][nt][3];
            if (bias) {
                float2 bv = *(const float2*)(bias + col);
                v0 += bv.x; v1 += bv.y; v2 += bv.x; v3 += bv.y;
            }
            if (do_gelu) {
                v0 = 0.5f * v0 * (1.0f + erff(v0 * 0.70710678f));
                v1 = 0.5f * v1 * (1.0f + erff(v1 * 0.70710678f));
                v2 = 0.5f * v2 * (1.0f + erff(v2 * 0.70710678f));
                v3 = 0.5f * v3 * (1.0f + erff(v3 * 0.70710678f));
            }
            size_t g0 = (size_t)r0 * N + col;
            size_t g1 = (size_t)(r0 + 8) * N + col;
            if (outf) {
                if (res) {
                    float2 ra = *(const float2*)(res + g0);
                    float2 rb = *(const float2*)(res + g1);
                    v0 += ra.x; v1 += ra.y; v2 += rb.x; v3 += rb.y;
                }
                float2 o0; o0.x = v0; o0.y = v1;
                float2 o1; o1.x = v2; o1.y = v3;
                *(float2*)(outf + g0) = o0;
                *(float2*)(outf + g1) = o1;
            } else {
                *(uint32_t*)(outh + g0) = pk2h(v0, v1);
                *(uint32_t*)(outh + g1) = pk2h(v2, v3);
            }
        }
    }
}

#define GSMEM128 (3*(GATILEB + 128*GROWB))   // 110592
#define GSMEM64  (3*(GATILEB + 64*GROWB))    // 82944

// ---------------------------------------------------------------------------
// Flash attention, fp16 mma.sync, no online max, Q pre-scaled at prep.
// 128 q per CTA, 256 threads. K/V 3-stage cp.async pipeline.
// ---------------------------------------------------------------------------
#define ASTR   72
#define AQTILE (128*ASTR*2)         // 18432 (Q: 128 rows)
#define AKTILE (64*ASTR*2)          // 9216  (K or V: 64 rows)
#define ASTG   (2*AKTILE)           // 18432 per stage
#define ANSTG  3
#define ASMEM  (AQTILE + ANSTG*ASTG)    // 73728

__global__ __launch_bounds__(256)
void attn_hp(const __half* __restrict__ QKV,
             __half* __restrict__ Y)
{
    extern __shared__ char smem[];
    const uint32_t sb = smem_u32(smem);
    const int tid = threadIdx.x, lane = tid & 31, wid = tid >> 5;
    const int q0 = blockIdx.x * 128, h = blockIdx.y, b = blockIdx.z;
    const size_t rowbase = (size_t)b * TT;
    const uint32_t kvbase = sb + AQTILE;

    #pragma unroll
    for (int i = 0; i < 4; ++i) {
        int id = tid + i * 256, row = id >> 3, c = id & 7;
        cpa16(sb + (uint32_t)row * 144 + c * 16,
              QKV + (rowbase + q0 + row) * QKVN + h * DHD + c * 8);
    }
    auto loadKV = [&](int s, int kt) {
        uint32_t base = kvbase + s * ASTG;
        #pragma unroll
        for (int i = 0; i < 2; ++i) {
            int id = tid + i * 256, row = id >> 3, c = id & 7;
            size_t gk = (rowbase + kt * 64 + row) * QKVN + 512 + h * DHD + c * 8;
            cpa16(base + (uint32_t)row * 144 + c * 16,          QKV + gk);
            cpa16(base + AKTILE + (uint32_t)row * 144 + c * 16, QKV + gk + 512);
        }
        cp_commit();
    };
    loadKV(0, 0);    // group 0: Q + stage0
    loadKV(1, 1);    // group 1: stage1

    const int lr = lane & 7;
    const uint32_t aoffQ = (uint32_t)((wid*16 + ((lane>>3)&1)*8 + lr) * ASTR + (lane>>4)*8) * 2;
    uint32_t boffK[4];
    #pragma unroll
    for (int p = 0; p < 4; ++p)
        boffK[p] = (uint32_t)((p*16 + (lane>>4)*8 + lr) * ASTR + ((lane>>3)&1)*8) * 2;
    const uint32_t voffV = (uint32_t)((lr + 8*((lane>>3)&1)) * ASTR + 8*(lane>>4)) * 2;

    uint32_t qf[4][4];
    float accs[8][4], acco[8][4];
    #pragma unroll
    for (int nt = 0; nt < 8; ++nt)
        #pragma unroll
        for (int j = 0; j < 4; ++j) acco[nt][j] = 0.0f;
    float lA = 0.0f, lB = 0.0f;

    const int NTK = TT / 64;
    int s_c = 0, s_l = 2;
    for (int kt = 0; kt < NTK; ++kt) {
        if (kt + 1 < NTK) cp_wait<1>();
        else              cp_wait<0>();
        __syncthreads();
        if (kt + 2 < NTK) {
            loadKV(s_l, kt + 2);
            if (++s_l == ANSTG) s_l = 0;
        }
        if (kt == 0) {
            #pragma unroll
            for (int ks = 0; ks < 4; ++ks) ldm4(qf[ks], sb + aoffQ + ks * 32);
        }
        uint32_t base = kvbase + s_c * ASTG;
        if (++s_c == ANSTG) s_c = 0;

        // ---- S = Q @ K^T (Q pre-scaled by 0.125*log2e) ----
        #pragma unroll
        for (int nt = 0; nt < 8; ++nt)
            #pragma unroll
            for (int j = 0; j < 4; ++j) accs[nt][j] = 0.0f;
        #pragma unroll
        for (int ks = 0; ks < 4; ++ks) {
            uint32_t kb = ks * 32;
            uint32_t kf[4][4];
            #pragma unroll
            for (int p = 0; p < 4; ++p) ldm4(kf[p], base + boffK[p] + kb);
            #pragma unroll
            for (int p = 0; p < 4; ++p) {
                mma16816(accs[p*2],   qf[ks], kf[p][0], kf[p][1]);
                mma16816(accs[p*2+1], qf[ks], kf[p][2], kf[p][3]);
            }
        }

        // ---- P = exp2(S) ----
        #pragma unroll
        for (int nt = 0; nt < 8; ++nt) {
            float p0 = exp2f(accs[nt][0]);
            float p1 = exp2f(accs[nt][1]);
            float p2 = exp2f(accs[nt][2]);
            float p3 = exp2f(accs[nt][3]);
            accs[nt][0] = p0; accs[nt][1] = p1;
            accs[nt][2] = p2; accs[nt][3] = p3;
            lA += p0 + p1; lB += p2 + p3;
        }

        // ---- O += P @ V ----
        #pragma unroll
        for (int j = 0; j < 4; ++j) {
            uint32_t pa[4];
            pa[0] = pk2h(accs[2*j][0],   accs[2*j][1]);
            pa[1] = pk2h(accs[2*j][2],   accs[2*j][3]);
            pa[2] = pk2h(accs[2*j+1][0], accs[2*j+1][1]);
            pa[3] = pk2h(accs[2*j+1][2], accs[2*j+1][3]);
            uint32_t vrow = j * 16 * (ASTR * 2);
            #pragma unroll
            for (int qd = 0; qd < 4; ++qd) {
                uint32_t vf[4];
                ldm4t(vf, base + AKTILE + voffV + vrow + qd * 32);
                mma16816(acco[qd*2],   pa, vf[0], vf[1]);
                mma16816(acco[qd*2+1], pa, vf[2], vf[3]);
            }
        }
    }

    lA += __shfl_xor_sync(0xffffffffu, lA, 1);
    lA += __shfl_xor_sync(0xffffffffu, lA, 2);
    lB += __shfl_xor_sync(0xffffffffu, lB, 1);
    lB += __shfl_xor_sync(0xffffffffu, lB, 2);

    float invA = 1.0f / lA, invB = 1.0f / lB;
    int rA = q0 + wid * 16 + (lane >> 2);
    #pragma unroll
    for (int nt = 0; nt < 8; ++nt) {
        int col = h * DHD + nt * 8 + (lane & 3) * 2;
        size_t g0 = (rowbase + rA) * CC + col;
        size_t g1 = (rowbase + rA + 8) * CC + col;
        *(uint32_t*)(Y + g0) = pk2h(acco[nt][0] * invA, acco[nt][1] * invA);
        *(uint32_t*)(Y + g1) = pk2h(acco[nt][2] * invB, acco[nt][3] * invB);
    }
}

// ---------------------------------------------------------------------------
// LayerNorm: warp-per-row, 8 rows/CTA
// ---------------------------------------------------------------------------
__global__ __launch_bounds__(256)
void ln_kernel(const float* __restrict__ x,
               const float* __restrict__ g,
               const float* __restrict__ b,
               __half* __restrict__ oh)
{
    const int lane = threadIdx.x & 31, wid = threadIdx.x >> 5;
    const int row = blockIdx.x * 8 + wid;
    const float4* xr = (const float4*)(x + (size_t)row * CC);

    float4 v[4];
    float s = 0.0f, s2 = 0.0f;
    #pragma unroll
    for (int i = 0; i < 4; ++i) {
        v[i] = xr[lane + i * 32];
        s  += v[i].x + v[i].y + v[i].z + v[i].w;
        s2 += v[i].x*v[i].x + v[i].y*v[i].y + v[i].z*v[i].z + v[i].w*v[i].w;
    }
    #pragma unroll
    for (int o = 16; o; o >>= 1) {
        s  += __shfl_xor_sync(0xffffffffu, s,  o);
        s2 += __shfl_xor_sync(0xffffffffu, s2, o);
    }
    float mu = s * (1.0f / CC);
    float var = s2 * (1.0f / CC) - mu * mu;
    float rstd = rsqrtf(var + 1e-5f);

    uint2* orow = (uint2*)(oh + (size_t)row * CC);
    #pragma unroll
    for (int i = 0; i < 4; ++i) {
        float4 gg = ((const float4*)g)[lane + i * 32];
        float4 bb = ((const float4*)b)[lane + i * 32];
        float h0 = (v[i].x - mu) * rstd * gg.x + bb.x;
        float h1 = (v[i].y - mu) * rstd * gg.y + bb.y;
        float h2 = (v[i].z - mu) * rstd * gg.z + bb.z;
        float h3 = (v[i].w - mu) * rstd * gg.w + bb.w;
        uint2 o; o.x = pk2h(h0, h1); o.y = pk2h(h2, h3);
        orow[lane + i * 32] = o;
    }
}

// ---------------------------------------------------------------------------
// Launch
// ---------------------------------------------------------------------------
extern "C" void kernel_launch(void* const* d_in, const int* in_sizes, int n_in,
                              void* d_out, int out_size)
{
    const int*   idx  = (const int*)  d_in[0];
    const float* tok  = (const float*)d_in[1];
    const float* pos  = (const float*)d_in[2];
    const float* ln1g = (const float*)d_in[3];
    const float* ln1b = (const float*)d_in[4];
    const float* Wq   = (const float*)d_in[5];
    const float* bq   = (const float*)d_in[6];
    const float* Wk   = (const float*)d_in[7];
    const float* bk   = (const float*)d_in[8];
    const float* Wv   = (const float*)d_in[9];
    const float* bv   = (const float*)d_in[10];
    const float* Wp   = (const float*)d_in[11];
    const float* bp   = (const float*)d_in[12];
    const float* ln2g = (const float*)d_in[13];
    const float* ln2b = (const float*)d_in[14];
    const float* W1   = (const float*)d_in[15];
    const float* b1   = (const float*)d_in[16];
    const float* W2   = (const float*)d_in[17];
    const float* b2   = (const float*)d_in[18];
    const float* lnfg = (const float*)d_in[19];
    const float* lnfb = (const float*)d_in[20];
    const float* Whd  = (const float*)d_in[21];
    float* out = (float*)d_out;

    float *x, *bqkv;
    __half *xn, *qkv, *y, *h, *w;
    cudaGetSymbolAddress((void**)&x,    g_x);
    cudaGetSymbolAddress((void**)&xn,   g_xn);
    cudaGetSymbolAddress((void**)&qkv,  g_qkv);
    cudaGetSymbolAddress((void**)&y,    g_y);
    cudaGetSymbolAddress((void**)&h,    g_h);
    cudaGetSymbolAddress((void**)&w,    g_w);
    cudaGetSymbolAddress((void**)&bqkv, g_bqkv);

    cudaFuncSetAttribute(gemm_t<128>, cudaFuncAttributeMaxDynamicSharedMemorySize, GSMEM128);
    cudaFuncSetAttribute(gemm_t<64>,  cudaFuncAttributeMaxDynamicSharedMemorySize, GSMEM64);
    cudaFuncSetAttribute(attn_hp, cudaFuncAttributeMaxDynamicSharedMemorySize, ASMEM);

    // ---- prep args: 13 weights (+scale) + bias + embed ----
    PrepArgs pa;
    int zi = 0;
    for (int l = 0; l < LLAY; l++) {
        pa.src[zi] = Wq + (size_t)l*CC*CC; pa.dst[zi] = OQKV + (size_t)l*QKVN*CC;           pa.K[zi]=CC; pa.N[zi]=CC; pa.scl[zi]=SCQ;  zi++;
        pa.src[zi] = Wk + (size_t)l*CC*CC; pa.dst[zi] = OQKV + (size_t)l*QKVN*CC + 512*CC;  pa.K[zi]=CC; pa.N[zi]=CC; pa.scl[zi]=1.0f; zi++;
        pa.src[zi] = Wv + (size_t)l*CC*CC; pa.dst[zi] = OQKV + (size_t)l*QKVN*CC + 1024*CC; pa.K[zi]=CC; pa.N[zi]=CC; pa.scl[zi]=1.0f; zi++;
        pa.src[zi] = Wp + (size_t)l*CC*CC; pa.dst[zi] = OP + (size_t)l*CC*CC;               pa.K[zi]=CC; pa.N[zi]=CC; pa.scl[zi]=1.0f; zi++;
        pa.src[zi] = W1 + (size_t)l*CC*FF; pa.dst[zi] = O1 + (size_t)l*CC*FF;               pa.K[zi]=CC; pa.N[zi]=FF; pa.scl[zi]=1.0f; zi++;
        pa.src[zi] = W2 + (size_t)l*FF*CC; pa.dst[zi] = O2 + (size_t)l*FF*CC;               pa.K[zi]=FF; pa.N[zi]=CC; pa.scl[zi]=1.0f; zi++;
    }
    pa.src[zi] = Whd; pa.dst[zi] = OHD; pa.K[zi]=CC; pa.N[zi]=VV; pa.scl[zi]=1.0f; zi++;
    pa.K[13] = 0; pa.N[13] = 0; pa.src[13] = nullptr; pa.dst[13] = 0; pa.scl[13] = 1.0f;
    pa.bq = bq; pa.bk = bk; pa.bv = bv;
    pa.off[0] = 0;
    for (int z = 0; z < 13; z++)
        pa.off[z + 1] = pa.off[z] + (pa.N[z] / 32) * (pa.K[z] / 32);
    pa.off[14] = pa.off[13] + 12;
    pa.off[15] = pa.off[14] + 1024;
    int nblocks = pa.off[15];

    dim3 tb(32, 8);
    dim3 gQKV(QKVN/128, MTOK/128);   // (12, 32) BN=128 (R14 best)
    dim3 gF(FF/128, MTOK/128);       // (16, 32) BN=128
    dim3 gC64(CC/64, MTOK/128);      // (8, 32)  BN=64
    dim3 gA(TT/128, HH, BB);         // (4, 8, 8) = 256
    dim3 gLN(MTOK/8);

    // launch 0: prep(+embed), 1: ln, 2: qkv, 3: attn (ncu capture target)
    prep_kernel<<<nblocks, tb>>>(pa, w, bqkv, idx, tok, pos, x);

    for (int s = 0; s < NSTEPS; s++) {
        for (int l = 0; l < LLAY; l++) {
            size_t lq = OQKV + (size_t)l * QKVN * CC;
            size_t lp = OP + (size_t)l * CC * CC;
            size_t l1 = O1 + (size_t)l * CC * FF;
            size_t l2 = O2 + (size_t)l * FF * CC;
            ln_kernel<<<gLN, 256>>>(x, ln1g + l*CC, ln1b + l*CC, xn);
            gemm_t<128><<<gQKV, 256, GSMEM128>>>(xn, w + lq, bqkv + l*QKVN, nullptr,
                                                 nullptr, qkv, QKVN, CC, 0);
            attn_hp<<<gA, 256, ASMEM>>>(qkv, y);
            gemm_t<64><<<gC64, 128, GSMEM64>>>(y, w + lp, bp + l*CC, x,
                                               x, nullptr, CC, CC, 0);
            ln_kernel<<<gLN, 256>>>(x, ln2g + l*CC, ln2b + l*CC, xn);
            gemm_t<128><<<gF, 256, GSMEM128>>>(xn, w + l1, b1 + l*FF, nullptr,
                                               nullptr, h, FF, CC, 1);
            gemm_t<64><<<gC64, 128, GSMEM64>>>(h, w + l2, b2 + l*CC, x,
                                               x, nullptr, CC, FF, 0);
        }
    }

    ln_kernel<<<gLN, 256>>>(x, lnfg, lnfb, xn);
    gemm_t<64><<<gC64, 128, GSMEM64>>>(xn, w + OHD, nullptr, nullptr,
                                       out, nullptr, VV, CC, 0);
}